// round 8
// baseline (speedup 1.0000x reference)
#include <cuda_runtime.h>
#include <cuda_bf16.h>
#include <cstdint>

// OctonionFanoCoherence (composition-algebra form, verified rel_err ~1.9e-6):
//   ||x̂i*x̂j - x̂k||^2 = 2 - 2*dot(omul(xi,xj), xk)*inv_i*inv_j*inv_k
//   avg_error = 2 - (2/7)*sum_l dot_l ; phi = clip(-log(avg+1e-8)*exp(ls),0,10)
//
// R8: packed f32x2 math (FFMA2) — each thread computes TWO batch elements,
// packing along the batch axis (identical sign structure, verbatim algebra).
// Warp-autonomous cp.async.cg staging (R7 layout: natural AoS order, zero
// write conflicts), no __syncthreads. Negations are 64-bit XORs (ALU pipe),
// keeping the fma pipe at 4 ops per quaternion component.

#define TPB      128
#define WARPS    (TPB / 32)
#define ELEM_F4  14                 // 14 float4 = 56 floats per element
#define WELEMS   64                 // elements per warp (2 per lane)
#define WTILE_F4 (ELEM_F4 * WELEMS) // 896 float4 = 14336 B per warp slice

typedef unsigned long long u64;
#define SGN2  0x8000000080000000ULL           // packed sign-flip mask
#define NEG1P 0xBF800000BF800000ULL           // packed (-1.0f, -1.0f)

__device__ __forceinline__ u64 f2mul(u64 a, u64 b) {
    u64 r; asm("mul.rn.f32x2 %0, %1, %2;" : "=l"(r) : "l"(a), "l"(b)); return r;
}
__device__ __forceinline__ u64 f2add(u64 a, u64 b) {
    u64 r; asm("add.rn.f32x2 %0, %1, %2;" : "=l"(r) : "l"(a), "l"(b)); return r;
}
__device__ __forceinline__ u64 f2fma(u64 a, u64 b, u64 c) {
    u64 r; asm("fma.rn.f32x2 %0, %1, %2, %3;" : "=l"(r) : "l"(a), "l"(b), "l"(c)); return r;
}
__device__ __forceinline__ u64 f2neg(u64 a) { return a ^ SGN2; }          // ALU pipe
__device__ __forceinline__ u64 f2sub(u64 a, u64 b) { return f2fma(b, NEG1P, a); }
__device__ __forceinline__ u64 f2pack(float lo, float hi) {
    u64 r; asm("mov.b64 %0, {%1, %2};" : "=l"(r) : "f"(lo), "f"(hi)); return r;
}
__device__ __forceinline__ void f2unpack(u64 a, float& lo, float& hi) {
    asm("mov.b64 {%0, %1}, %2;" : "=f"(lo), "=f"(hi) : "l"(a));
}

// Packed quaternion multiply — sign pattern transcribed from the VERIFIED
// scalar qmul (rounds 1/3/4). Each component: 1 mul + 3 fma (fma pipe) + 1 xor.
//   r0 = p0q0 - p1q1 - p2q2 - p3q3
//   r1 = p0q1 + p1q0 + p2q3 - p3q2
//   r2 = p0q2 - p1q3 + p2q0 + p3q1
//   r3 = p0q3 + p1q2 - p2q1 + p3q0
__device__ __forceinline__ void qmul_p(const u64* p, const u64* q, u64* r) {
    u64 a;
    a = f2mul(p[1], q[1]); a = f2fma(p[2], q[2], a); a = f2fma(p[3], q[3], a);
    r[0] = f2fma(p[0], q[0], f2neg(a));
    a = f2neg(f2mul(p[3], q[2])); a = f2fma(p[2], q[3], a); a = f2fma(p[1], q[0], a);
    r[1] = f2fma(p[0], q[1], a);
    a = f2neg(f2mul(p[1], q[3])); a = f2fma(p[2], q[0], a); a = f2fma(p[3], q[1], a);
    r[2] = f2fma(p[0], q[2], a);
    a = f2neg(f2mul(p[2], q[1])); a = f2fma(p[1], q[2], a); a = f2fma(p[3], q[0], a);
    r[3] = f2fma(p[0], q[3], a);
}

// Packed octonion multiply — verbatim structure of verified omul:
//   z1 = a1*b1 - conj(b2)*a2 ;  z2 = b2*a1 + a2*conj(b1)
__device__ __forceinline__ void omul_p(const u64* x, const u64* y, u64* z) {
    const u64* a1 = x;     const u64* a2 = x + 4;
    const u64* b1 = y;     const u64* b2 = y + 4;
    u64 t1[4], t2[4];
    qmul_p(a1, b1, t1);
    u64 cb2[4] = { b2[0], f2neg(b2[1]), f2neg(b2[2]), f2neg(b2[3]) };
    qmul_p(cb2, a2, t2);
    z[0] = f2sub(t1[0], t2[0]); z[1] = f2sub(t1[1], t2[1]);
    z[2] = f2sub(t1[2], t2[2]); z[3] = f2sub(t1[3], t2[3]);
    qmul_p(b2, a1, t1);
    u64 cb1[4] = { b1[0], f2neg(b1[1]), f2neg(b1[2]), f2neg(b1[3]) };
    qmul_p(a2, cb1, t2);
    z[4] = f2add(t1[0], t2[0]); z[5] = f2add(t1[1], t2[1]);
    z[6] = f2add(t1[2], t2[2]); z[7] = f2add(t1[3], t2[3]);
}

__global__ void __launch_bounds__(TPB, 3)
oct_fano_kernel(const float* __restrict__ in,
                const float* __restrict__ log_sens,
                float* __restrict__ out,
                int B)
{
    __shared__ float4 s[WARPS][WTILE_F4];   // 4 * 14336 = 57344 B -> 3 CTAs/SM

    const int lane = threadIdx.x & 31;
    const int wid  = threadIdx.x >> 5;
    const long long warpBase =
        ((long long)blockIdx.x * WARPS + wid) * WELEMS;  // first of 64 elements

    const float esens = expf(__ldg(log_sens));           // overlaps loads

    const int elems = (int)min((long long)WELEMS, (long long)B - warpBase);
    if (elems <= 0) return;
    const int n4 = elems * ELEM_F4;

    // ---- Stage 1: warp-coalesced cp.async.cg, natural-order dst (R7) ----
    const float4* src = reinterpret_cast<const float4*>(in) + warpBase * ELEM_F4;
    const uint32_t sbase = (uint32_t)__cvta_generic_to_shared(&s[wid][0]);
#pragma unroll
    for (int it = 0; it < WTILE_F4 / 32; ++it) {          // 28 iterations
        int idx4 = lane + it * 32;
        if (idx4 < n4) {
            asm volatile("cp.async.cg.shared.global [%0], [%1], 16;\n"
                         :: "r"(sbase + (uint32_t)idx4 * 16u), "l"(src + idx4)
                         : "memory");
        }
    }
    asm volatile("cp.async.commit_group;\n" ::: "memory");
    asm volatile("cp.async.wait_group 0;\n" ::: "memory");
    __syncwarp();

    // ---- Stage 2: read elements e0=lane, e1=lane+32; pack along batch ----
    u64 x[56];
    {
        const float4* bufA = &s[wid][lane * ELEM_F4];
        const float4* bufB = &s[wid][(lane + 32) * ELEM_F4];
#pragma unroll
        for (int i = 0; i < ELEM_F4; ++i) {
            float4 a = bufA[i];
            float4 b = bufB[i];
            x[4*i + 0] = f2pack(a.x, b.x);
            x[4*i + 1] = f2pack(a.y, b.y);
            x[4*i + 2] = f2pack(a.z, b.z);
            x[4*i + 3] = f2pack(a.w, b.w);
        }
    }

    // ---- Inverse norms (rsqrt per half; == 1/max(||x||,1e-12)) ----
    u64 inv[7];
#pragma unroll
    for (int l = 0; l < 7; ++l) {
        u64 acc = f2mul(x[l*8], x[l*8]);
#pragma unroll
        for (int c = 1; c < 8; ++c)
            acc = f2fma(x[l*8 + c], x[l*8 + c], acc);
        float na, nb;
        f2unpack(acc, na, nb);
        inv[l] = f2pack(rsqrtf(fmaxf(na, 1e-24f)), rsqrtf(fmaxf(nb, 1e-24f)));
    }

    // ---- Fano lines (l, l+1 mod 7, l+3 mod 7) ----
    u64 sacc = 0;   // packed (0.0f, 0.0f)
#pragma unroll
    for (int l = 0; l < 7; ++l) {
        const int i = l, j = (l + 1) % 7, k = (l + 3) % 7;
        u64 p[8];
        omul_p(&x[i*8], &x[j*8], p);
        const u64* xk = &x[k*8];
        u64 d = f2mul(p[0], xk[0]);
#pragma unroll
        for (int c = 1; c < 8; ++c)
            d = f2fma(p[c], xk[c], d);
        u64 w = f2mul(f2mul(inv[i], inv[j]), inv[k]);
        sacc = f2fma(d, w, sacc);
    }

    // ---- Epilogue: unpack, finish scalar, two coalesced stores ----
    float s0, s1;
    f2unpack(sacc, s0, s1);

    float avg0 = fmaf(s0, -2.0f / 7.0f, 2.0f);
    float phi0 = -logf(avg0 + 1e-8f) * esens;
    phi0 = fminf(fmaxf(phi0, 0.0f), 10.0f);
    if (lane < elems) out[warpBase + lane] = phi0;

    float avg1 = fmaf(s1, -2.0f / 7.0f, 2.0f);
    float phi1 = -logf(avg1 + 1e-8f) * esens;
    phi1 = fminf(fmaxf(phi1, 0.0f), 10.0f);
    if (lane + 32 < elems) out[warpBase + 32 + lane] = phi1;
}

extern "C" void kernel_launch(void* const* d_in, const int* in_sizes, int n_in,
                              void* d_out, int out_size)
{
    const float* colony   = (const float*)d_in[0];   // [B, 7, 8] fp32
    const float* log_sens = (const float*)d_in[1];   // scalar fp32
    float* out = (float*)d_out;                      // [B] fp32

    int B = in_sizes[0] / 56;
    long long per_cta = (long long)WELEMS * WARPS;   // 256 elements per CTA
    int blocks = (int)((B + per_cta - 1) / per_cta);
    oct_fano_kernel<<<blocks, TPB>>>(colony, log_sens, out, B);
}